// round 13
// baseline (speedup 1.0000x reference)
#include <cuda_runtime.h>
#include <cstdint>

// Problem constants
#define BATCH 64
#define TSTEPS 2048
#define DIN 128
#define HID 256
#define DOUT 128
#define G4H (4*HID)        // 1024

// Scan tiling: 16 column-groups x 8 batch-groups = 128 CTAs
#define NCTA 128
#define JPC 16             // hidden units per CTA
#define NCOL 64            // gate columns per CTA
#define BPC 8              // batches per CTA
#define NWARP 16           // 16 warps: warp = k-chunk of 16, 1:1 with producer
#define KC 16              // K per warp
#define NTH_SCAN 512

// scan SMEM (floats)
#define PSTR 70
#define S_H     0                         // sH [k(256)][b(8)] = 2048
#define S_PART  (S_H + 256*8)             // 2 x 16 x 8 x PSTR = 17920
#define S_C     (S_PART + 2*NWARP*BPC*PSTR)
#define S_FLOATS (S_C + 128)
#define S_SMEM_BYTES (S_FLOATS*4)         // ~81 KB

// x_proj kernel smem
#define NTHREADS 256
#define XP_XSTRIDE 133
#define XP_WSTRIDE 132
#define XPK_SX    0
#define XPK_SW    (128*XP_XSTRIDE)
#define XPK_FLOATS (XPK_SW + 128*XP_WSTRIDE)
#define XPK_BYTES (XPK_FLOATS*4)

// Global scratch
__device__ __align__(16) float g_xp[(size_t)TSTEPS * 16 * 8 * 512];   // [t][cg][bg][bb*64+c]
// tagged h words {hi32 = step tag, lo32 = h bits}: [buf][bg][cg][lj*8+bb]
__device__ __align__(16) unsigned long long g_hx[2][8][16][JPC*BPC];

__device__ __forceinline__ uint32_t smem_u32(const void* p) {
    return (uint32_t)__cvta_generic_to_shared(p);
}
__device__ __forceinline__ float fast_sig(float e) {   // e = expf(-x)
    return __fdividef(1.0f, 1.0f + e);
}
__device__ __forceinline__ unsigned long long ld_relaxed_u64(
        const unsigned long long* p) {
    unsigned long long v;
    asm volatile("ld.relaxed.gpu.global.u64 %0, [%1];"
                 : "=l"(v) : "l"(p) : "memory");
    return v;
}

// ---------------------------------------------------------------------------
__global__ void init_kernel() {
    int i = blockIdx.x * blockDim.x + threadIdx.x;
    int total = 2 * 8 * 16 * JPC * BPC;
    if (i < total) ((unsigned long long*)g_hx)[i] = 0ull;  // tag 0, h = 0
}

// ---------------------------------------------------------------------------
// x_proj: g_xp[t][cg][bg][bb*64 + gate*16+lj] = x[b,t,:] . W_x[:, gcol] + bias
// ---------------------------------------------------------------------------
__global__ void __launch_bounds__(NTHREADS, 1)
xproj_kernel(const float* __restrict__ x,
             const float* __restrict__ W_x,
             const float* __restrict__ bias) {
    extern __shared__ float smem[];
    float* sX = smem + XPK_SX;
    float* sW = smem + XPK_SW;

    const int tid  = threadIdx.x;
    const int tblk = blockIdx.x;
    const int bg   = blockIdx.y;

    for (int idx = tid; idx < 128 * 32; idx += NTHREADS) {
        int r = idx >> 5, f4 = idx & 31;
        int tt = r >> 3, bb = r & 7;
        int b = bg * 8 + bb, t = tblk * 16 + tt;
        float4 v = __ldg(reinterpret_cast<const float4*>(
            x + ((size_t)b * TSTEPS + t) * DIN) + f4);
        float* dst = sX + r * XP_XSTRIDE + f4 * 4;
        dst[0] = v.x; dst[1] = v.y; dst[2] = v.z; dst[3] = v.w;
    }

    const int cq = tid & 7;
    const int rg = tid >> 3;

    for (int p = 0; p < 8; p++) {
        const int cp0 = p * 128;
        __syncthreads();
        for (int idx = tid; idx < 128 * 32; idx += NTHREADS) {
            int d = idx >> 5, c4 = idx & 31;
            float4 v = __ldg(reinterpret_cast<const float4*>(
                W_x + (size_t)d * G4H + cp0) + c4);
            float* dst = sW + d * XP_WSTRIDE + c4 * 4;
            dst[0] = v.x; dst[1] = v.y; dst[2] = v.z; dst[3] = v.w;
        }
        __syncthreads();

        unsigned long long acc[4][8];
        #pragma unroll
        for (int qq = 0; qq < 8; qq++) {
            float2 bv = __ldg(reinterpret_cast<const float2*>(
                bias + cp0 + 2 * (cq + 8 * qq)));
            unsigned long long bu;
            asm("mov.b64 %0, {%1, %2};" : "=l"(bu) : "f"(bv.x), "f"(bv.y));
            #pragma unroll
            for (int rr = 0; rr < 4; rr++) acc[rr][qq] = bu;
        }

        #pragma unroll 4
        for (int d = 0; d < 128; d++) {
            unsigned long long x2[4];
            #pragma unroll
            for (int rr = 0; rr < 4; rr++) {
                float xv = sX[(rg * 4 + rr) * XP_XSTRIDE + d];
                asm("mov.b64 %0, {%1, %1};" : "=l"(x2[rr]) : "f"(xv));
            }
            const uint32_t wrow = smem_u32(sW + d * XP_WSTRIDE + 2 * cq);
            #pragma unroll
            for (int qq = 0; qq < 8; qq++) {
                unsigned long long w2;
                asm volatile("ld.shared.u64 %0, [%1];"
                             : "=l"(w2) : "r"(wrow + qq * 64));
                #pragma unroll
                for (int rr = 0; rr < 4; rr++)
                    asm volatile("fma.rn.f32x2 %0, %1, %2, %0;"
                                 : "+l"(acc[rr][qq]) : "l"(x2[rr]), "l"(w2));
            }
        }

        #pragma unroll
        for (int rr = 0; rr < 4; rr++) {
            int r = rg * 4 + rr;
            int tt = r >> 3, bb = r & 7;
            int t = tblk * 16 + tt;
            #pragma unroll
            for (int qq = 0; qq < 8; qq++) {
                int cglob = cp0 + 2 * (cq + 8 * qq);
                int gate = cglob >> 8, rem = cglob & 255;
                int cg = rem >> 4, lj = rem & 15;
                float lo, hi;
                asm("mov.b64 {%0,%1}, %2;" : "=f"(lo), "=f"(hi) : "l"(acc[rr][qq]));
                float2* dst = reinterpret_cast<float2*>(
                    g_xp + ((size_t)((t * 16 + cg) * 8 + bg)) * 512
                         + bb * 64 + gate * 16 + lj);
                *dst = make_float2(lo, hi);
            }
        }
    }
}

// ---------------------------------------------------------------------------
// persistent LSTM scan: 512 threads, 16 warps (warp = 16-k chunk, one
// producer each); W in regs from global; 2-deep pipelined tag poll;
// barrier-split helpers-run-ahead.
// ---------------------------------------------------------------------------
__global__ void __launch_bounds__(NTH_SCAN, 1)
lstm_scan_kernel(const float* __restrict__ W_h) {
    extern __shared__ float smem[];
    float* sH    = smem + S_H;      // [k(256)][b(8)]
    float* sPart = smem + S_PART;   // [buf][w(16)][b(8)][c] stride PSTR
    float* sC    = smem + S_C;      // [lj*8+bb]

    const int tid = threadIdx.x;
    const int cg  = blockIdx.x & 15;
    const int bg  = blockIdx.x >> 4;
    const int j0  = cg * JPC;

    const int w    = tid >> 5;            // warp = k-chunk 0..15
    const int lane = tid & 31;
    const int hw   = lane >> 4;           // batch half
    const int lc   = lane & 15;           // owns cols 4lc..4lc+3
    const int k0   = w * KC;
    const int c0   = 4 * lc;

    // ---- W_h slice direct global -> regs (setup only)
    unsigned long long wreg[2][KC];       // [pair][k]
    {
        const int gate = c0 >> 4;
        const int ljw  = c0 & 15;
        const float* wp = W_h + (size_t)k0 * G4H + gate * HID + j0 + ljw;
        #pragma unroll
        for (int k = 0; k < KC; k++) {
            float4 wv = __ldg(reinterpret_cast<const float4*>(
                wp + (size_t)k * G4H));
            asm("mov.b64 %0, {%1, %2};" : "=l"(wreg[0][k]) : "f"(wv.x), "f"(wv.y));
            asm("mov.b64 %0, {%1, %2};" : "=l"(wreg[1][k]) : "f"(wv.z), "f"(wv.w));
        }
    }
    if (tid < JPC * BPC) sC[tid] = 0.0f;
    __syncthreads();

    const uint32_t hbase  = smem_u32(sH + k0 * BPC + 4 * hw);
    const uint32_t hstore = smem_u32(sH + k0 * BPC) + lane * 16;

    const int lj = tid >> 3;              // epilogue decode (tid<128)
    const int bb = tid & 7;

    for (int s = 0; s < TSTEPS; s++) {
        const int rbuf = s & 1;
        float* sP = sPart + rbuf * (NWARP * BPC * PSTR);

        // ---- prefetch x_proj gate inputs for epilogue (tid<128)
        float xr[4];
        if (tid < JPC * BPC) {
            const float* xpb = g_xp + ((size_t)((s * 16 + cg) * 8 + bg)) * 512
                             + bb * 64 + lj;
            #pragma unroll
            for (int gate = 0; gate < 4; gate++)
                xr[gate] = __ldg(xpb + gate * 16);
        }

        // ---- 2-deep pipelined poll on my single producer block
        const unsigned long long* pW = &g_hx[rbuf][bg][w][4 * lane];
        unsigned long long u[4], v[4];
        const unsigned exp_tag = (unsigned)s;
        #pragma unroll
        for (int i = 0; i < 4; i++) u[i] = ld_relaxed_u64(pW + i);
        #pragma unroll
        for (int i = 0; i < 4; i++) v[i] = ld_relaxed_u64(pW + i);
        for (;;) {
            bool oku = ((unsigned)(u[0] >> 32) == exp_tag) &&
                       ((unsigned)(u[1] >> 32) == exp_tag) &&
                       ((unsigned)(u[2] >> 32) == exp_tag) &&
                       ((unsigned)(u[3] >> 32) == exp_tag);
            if (__all_sync(0xffffffffu, oku)) break;
            #pragma unroll
            for (int i = 0; i < 4; i++) u[i] = ld_relaxed_u64(pW + i);
            bool okv = ((unsigned)(v[0] >> 32) == exp_tag) &&
                       ((unsigned)(v[1] >> 32) == exp_tag) &&
                       ((unsigned)(v[2] >> 32) == exp_tag) &&
                       ((unsigned)(v[3] >> 32) == exp_tag);
            if (__all_sync(0xffffffffu, okv)) {
                #pragma unroll
                for (int i = 0; i < 4; i++) u[i] = v[i];
                break;
            }
            #pragma unroll
            for (int i = 0; i < 4; i++) v[i] = ld_relaxed_u64(pW + i);
        }

        // ---- stage my block (one STS.128 covers 4 consecutive words)
        asm volatile("st.shared.v4.f32 [%0], {%1,%2,%3,%4};"
                     :: "r"(hstore),
                        "f"(__uint_as_float((unsigned)u[0])),
                        "f"(__uint_as_float((unsigned)u[1])),
                        "f"(__uint_as_float((unsigned)u[2])),
                        "f"(__uint_as_float((unsigned)u[3])));
        __syncwarp();

        // ---- GEMM: per k: 1 broadcast LDS.128 + 4 splats + 8 FMA2, 16 k
        unsigned long long acc[2][4];
        #pragma unroll
        for (int p = 0; p < 2; p++)
            #pragma unroll
            for (int i = 0; i < 4; i++) acc[p][i] = 0ull;

        #pragma unroll
        for (int k = 0; k < KC; k++) {
            float h0, h1, h2f, h3;
            asm volatile("ld.shared.v4.f32 {%0,%1,%2,%3}, [%4];"
                         : "=f"(h0), "=f"(h1), "=f"(h2f), "=f"(h3)
                         : "r"(hbase + k * 32));
            unsigned long long hh[4];
            asm("mov.b64 %0, {%1, %1};" : "=l"(hh[0]) : "f"(h0));
            asm("mov.b64 %0, {%1, %1};" : "=l"(hh[1]) : "f"(h1));
            asm("mov.b64 %0, {%1, %1};" : "=l"(hh[2]) : "f"(h2f));
            asm("mov.b64 %0, {%1, %1};" : "=l"(hh[3]) : "f"(h3));
            #pragma unroll
            for (int i = 0; i < 4; i++) {
                asm volatile("fma.rn.f32x2 %0, %1, %2, %0;"
                             : "+l"(acc[0][i]) : "l"(hh[i]), "l"(wreg[0][k]));
                asm volatile("fma.rn.f32x2 %0, %1, %2, %0;"
                             : "+l"(acc[1][i]) : "l"(hh[i]), "l"(wreg[1][k]));
            }
        }

        // ---- write partials
        #pragma unroll
        for (int i = 0; i < 4; i++) {
            int row = (w * BPC + 4 * hw + i) * PSTR;
            *reinterpret_cast<unsigned long long*>(sP + row + c0)     = acc[0][i];
            *reinterpret_cast<unsigned long long*>(sP + row + c0 + 2) = acc[1][i];
        }

        // ---- barrier split: epi warps (0-3) sync; helpers arrive & run ahead
        if (tid < JPC * BPC) {
            if ((s & 1) == 0)
                asm volatile("bar.sync 1, %0;" :: "n"(NTH_SCAN) : "memory");
            else
                asm volatile("bar.sync 2, %0;" :: "n"(NTH_SCAN) : "memory");

            // epilogue: reduce 16 partials, activations, tagged publish
            float g4[4];
            #pragma unroll
            for (int gate = 0; gate < 4; gate++) {
                int c = gate * JPC + lj;
                float vv = xr[gate];
                #pragma unroll
                for (int q = 0; q < NWARP; q++)
                    vv += sP[(q * BPC + bb) * PSTR + c];
                g4[gate] = vv;
            }
            float e0 = __expf(-g4[0]);
            float e1 = __expf(-g4[1]);
            float e2 = __expf(-2.0f * g4[2]);
            float e3 = __expf(-g4[3]);
            float ig = fast_sig(e0);
            float fg = fast_sig(e1);
            float gg = __fdividef(2.0f, 1.0f + e2) - 1.0f;
            float og = fast_sig(e3);
            float cnew = fg * sC[tid] + ig * gg;
            sC[tid] = cnew;
            float ech = __expf(-2.0f * cnew);
            float hnew = og * (__fdividef(2.0f, 1.0f + ech) - 1.0f);

            unsigned long long pk;
            asm("mov.b64 %0, {%1, %2};"
                : "=l"(pk) : "r"(__float_as_uint(hnew)), "r"((unsigned)(s + 1)));
            asm volatile("st.relaxed.gpu.global.u64 [%0], %1;"
                         :: "l"(&g_hx[rbuf ^ 1][bg][cg][tid]), "l"(pk)
                         : "memory");
        } else {
            if ((s & 1) == 0)
                asm volatile("bar.arrive 1, %0;" :: "n"(NTH_SCAN) : "memory");
            else
                asm volatile("bar.arrive 2, %0;" :: "n"(NTH_SCAN) : "memory");
            // helpers run ahead into step s+1 (sH rows warp-private,
            // sPart double-buffered; data deps bound skew to < 2 steps)
        }
    }
}

// ---------------------------------------------------------------------------
// final FC: out[b][d] = sum_k h_final[k][b] * fc_w[k][d] + fc_b[d]
// h_2048 (tag 2048) lives in g_hx[0][bg][k>>4][(k&15)*8+bb] low bits
// ---------------------------------------------------------------------------
__global__ void fc_kernel(const float* __restrict__ fc_w,
                          const float* __restrict__ fc_b,
                          float* __restrict__ out) {
    int b = blockIdx.x;
    int d = threadIdx.x;
    int bg = b >> 3, bb = b & 7;
    float acc = fc_b[d];
    #pragma unroll 8
    for (int k = 0; k < HID; k++) {
        unsigned long long v = g_hx[0][bg][k >> 4][(k & 15) * 8 + bb];
        acc += __uint_as_float((unsigned)v) * fc_w[k * DOUT + d];
    }
    out[b * DOUT + d] = acc;
}

// ---------------------------------------------------------------------------
extern "C" void kernel_launch(void* const* d_in, const int* in_sizes, int n_in,
                              void* d_out, int out_size) {
    const float* x    = (const float*)d_in[0];
    const float* W_x  = (const float*)d_in[1];
    const float* W_h  = (const float*)d_in[2];
    const float* bvec = (const float*)d_in[3];
    const float* fc_w = (const float*)d_in[4];
    const float* fc_b = (const float*)d_in[5];
    float* out = (float*)d_out;

    cudaFuncSetAttribute(xproj_kernel,
                         cudaFuncAttributeMaxDynamicSharedMemorySize, XPK_BYTES);
    cudaFuncSetAttribute(lstm_scan_kernel,
                         cudaFuncAttributeMaxDynamicSharedMemorySize, S_SMEM_BYTES);

    init_kernel<<<(2 * 8 * 16 * JPC * BPC + 255) / 256, 256>>>();
    xproj_kernel<<<dim3(TSTEPS / 16, 8), NTHREADS, XPK_BYTES>>>(x, W_x, bvec);
    lstm_scan_kernel<<<NCTA, NTH_SCAN, S_SMEM_BYTES>>>(W_h);
    fc_kernel<<<BATCH, DOUT>>>(fc_w, fc_b, out);
}

// round 14
// speedup vs baseline: 1.2009x; 1.2009x over previous
#include <cuda_runtime.h>
#include <cstdint>

// Problem constants
#define BATCH 64
#define TSTEPS 2048
#define DIN 128
#define HID 256
#define DOUT 128
#define G4H (4*HID)        // 1024

// Scan tiling: 16 column-groups x 8 batch-groups = 128 CTAs
#define NCTA 128
#define JPC 16             // hidden units per CTA
#define NCOL 64            // gate columns per CTA
#define BPC 8              // batches per CTA
#define KC 32              // K per warp (8 warps)
#define NTHREADS 256

// SMEM (floats)
#define SWSTR 66                         // sW2 [k][c] staging stride
#define PSTR 70                          // sPart row stride
#define SM_SW2   0                       // 256*66 = 16896 (setup only)
#define SM_H     (SM_SW2 + 256*SWSTR)    // sH [k(256)][b(8)] = 2048
#define SM_PART  (SM_H + 256*8)          // 2 x 8 x 8 x PSTR = 8960
#define SM_C     (SM_PART + 2*8*8*PSTR)  // 128
#define SM_FLOATS (SM_C + 128)
#define SMEM_BYTES (SM_FLOATS*4)         // ~113 KB

// x_proj kernel smem
#define XP_XSTRIDE 133
#define XP_WSTRIDE 132
#define XPK_SX    0
#define XPK_SW    (128*XP_XSTRIDE)
#define XPK_FLOATS (XPK_SW + 128*XP_WSTRIDE)
#define XPK_BYTES (XPK_FLOATS*4)

// Global scratch
__device__ __align__(16) float g_xp[(size_t)TSTEPS * 16 * 8 * 512];      // [t][cg][bg][bb*64+c]
// tagged h words: {hi32 = step tag, lo32 = h bits}; [buf][bg][cg][lj*8+bb]
__device__ __align__(16) unsigned long long g_hx[2][8][16][JPC*BPC];

__device__ __forceinline__ uint32_t smem_u32(const void* p) {
    return (uint32_t)__cvta_generic_to_shared(p);
}
__device__ __forceinline__ float fast_sig(float e) {   // e = expf(-x)
    return __fdividef(1.0f, 1.0f + e);
}
__device__ __forceinline__ unsigned long long ld_relaxed_u64(
        const unsigned long long* p) {
    unsigned long long v;
    asm volatile("ld.relaxed.gpu.global.u64 %0, [%1];"
                 : "=l"(v) : "l"(p) : "memory");
    return v;
}

// ---------------------------------------------------------------------------
__global__ void init_kernel() {
    int i = blockIdx.x * blockDim.x + threadIdx.x;
    int total = 2 * 8 * 16 * JPC * BPC;
    if (i < total) ((unsigned long long*)g_hx)[i] = 0ull;  // tag 0, h = 0
}

// ---------------------------------------------------------------------------
// x_proj: g_xp[t][cg][bg][bb*64 + gate*16+lj] = x[b,t,:] . W_x[:, gcol] + bias
// ---------------------------------------------------------------------------
__global__ void __launch_bounds__(NTHREADS, 1)
xproj_kernel(const float* __restrict__ x,
             const float* __restrict__ W_x,
             const float* __restrict__ bias) {
    extern __shared__ float smem[];
    float* sX = smem + XPK_SX;
    float* sW = smem + XPK_SW;

    const int tid  = threadIdx.x;
    const int tblk = blockIdx.x;
    const int bg   = blockIdx.y;

    for (int idx = tid; idx < 128 * 32; idx += NTHREADS) {
        int r = idx >> 5, f4 = idx & 31;
        int tt = r >> 3, bb = r & 7;
        int b = bg * 8 + bb, t = tblk * 16 + tt;
        float4 v = __ldg(reinterpret_cast<const float4*>(
            x + ((size_t)b * TSTEPS + t) * DIN) + f4);
        float* dst = sX + r * XP_XSTRIDE + f4 * 4;
        dst[0] = v.x; dst[1] = v.y; dst[2] = v.z; dst[3] = v.w;
    }

    const int cq = tid & 7;
    const int rg = tid >> 3;

    for (int p = 0; p < 8; p++) {
        const int cp0 = p * 128;
        __syncthreads();
        for (int idx = tid; idx < 128 * 32; idx += NTHREADS) {
            int d = idx >> 5, c4 = idx & 31;
            float4 v = __ldg(reinterpret_cast<const float4*>(
                W_x + (size_t)d * G4H + cp0) + c4);
            float* dst = sW + d * XP_WSTRIDE + c4 * 4;
            dst[0] = v.x; dst[1] = v.y; dst[2] = v.z; dst[3] = v.w;
        }
        __syncthreads();

        unsigned long long acc[4][8];
        #pragma unroll
        for (int qq = 0; qq < 8; qq++) {
            float2 bv = __ldg(reinterpret_cast<const float2*>(
                bias + cp0 + 2 * (cq + 8 * qq)));
            unsigned long long bu;
            asm("mov.b64 %0, {%1, %2};" : "=l"(bu) : "f"(bv.x), "f"(bv.y));
            #pragma unroll
            for (int rr = 0; rr < 4; rr++) acc[rr][qq] = bu;
        }

        #pragma unroll 4
        for (int d = 0; d < 128; d++) {
            unsigned long long x2[4];
            #pragma unroll
            for (int rr = 0; rr < 4; rr++) {
                float xv = sX[(rg * 4 + rr) * XP_XSTRIDE + d];
                asm("mov.b64 %0, {%1, %1};" : "=l"(x2[rr]) : "f"(xv));
            }
            const uint32_t wrow = smem_u32(sW + d * XP_WSTRIDE + 2 * cq);
            #pragma unroll
            for (int qq = 0; qq < 8; qq++) {
                unsigned long long w2;
                asm volatile("ld.shared.u64 %0, [%1];"
                             : "=l"(w2) : "r"(wrow + qq * 64));
                #pragma unroll
                for (int rr = 0; rr < 4; rr++)
                    asm volatile("fma.rn.f32x2 %0, %1, %2, %0;"
                                 : "+l"(acc[rr][qq]) : "l"(x2[rr]), "l"(w2));
            }
        }

        #pragma unroll
        for (int rr = 0; rr < 4; rr++) {
            int r = rg * 4 + rr;
            int tt = r >> 3, bb = r & 7;
            int t = tblk * 16 + tt;
            #pragma unroll
            for (int qq = 0; qq < 8; qq++) {
                int cglob = cp0 + 2 * (cq + 8 * qq);
                int gate = cglob >> 8, rem = cglob & 255;
                int cg = rem >> 4, lj = rem & 15;
                float lo, hi;
                asm("mov.b64 {%0,%1}, %2;" : "=f"(lo), "=f"(hi) : "l"(acc[rr][qq]));
                float2* dst = reinterpret_cast<float2*>(
                    g_xp + ((size_t)((t * 16 + cg) * 8 + bg)) * 512
                         + bb * 64 + gate * 16 + lj);
                *dst = make_float2(lo, hi);
            }
        }
    }
}

// ---------------------------------------------------------------------------
// persistent LSTM scan: W_h in registers; self-tagging h words;
// 2-deep pipelined bulk poll; barrier-split helpers-run-ahead.
// ---------------------------------------------------------------------------
__global__ void __launch_bounds__(NTHREADS, 1)
lstm_scan_kernel(const float* __restrict__ W_h) {
    extern __shared__ float smem[];
    float* sW2   = smem + SM_SW2;   // [k][c] staging (setup only)
    float* sH    = smem + SM_H;     // [k(256)][b(8)]
    float* sPart = smem + SM_PART;  // [buf][w][b][c] stride PSTR
    float* sC    = smem + SM_C;     // [lj*8+bb]

    const int tid = threadIdx.x;
    const int cg  = blockIdx.x & 15;
    const int bg  = blockIdx.x >> 4;
    const int j0  = cg * JPC;

    // ---- stage W_h slice as [k][c] then load into registers
    for (int idx = tid; idx < KC * 8 * NCOL; idx += NTHREADS) {
        int k = idx >> 6, c = idx & 63;
        int gate = c >> 4, lj = c & 15;
        sW2[k * SWSTR + c] = W_h[(size_t)k * G4H + gate * HID + j0 + lj];
    }
    if (tid < JPC * BPC) sC[tid] = 0.0f;
    __syncthreads();

    const int w    = tid >> 5;            // warp = k-chunk
    const int lane = tid & 31;
    const int hw   = lane >> 4;           // batch half
    const int lc   = lane & 15;           // owns cols 4lc..4lc+3
    const int k0   = w * KC;
    const int c0   = 4 * lc;

    unsigned long long wreg[2][KC];       // [pair][k]
    {
        const uint32_t wb = smem_u32(sW2 + k0 * SWSTR + c0);
        #pragma unroll
        for (int k = 0; k < KC; k++) {
            asm volatile("ld.shared.u64 %0, [%1];"
                         : "=l"(wreg[0][k]) : "r"(wb + k * (SWSTR * 4)));
            asm volatile("ld.shared.u64 %0, [%1];"
                         : "=l"(wreg[1][k]) : "r"(wb + k * (SWSTR * 4) + 8));
        }
    }
    __syncthreads();   // sW2 dead after this

    const uint32_t hbase  = smem_u32(sH + k0 * BPC + 4 * hw);
    const uint32_t hstore = smem_u32(sH + k0 * BPC) + lane * 16;

    const int lj = tid >> 3;              // epilogue decode (tid<128)
    const int bb = tid & 7;

    for (int s = 0; s < TSTEPS; s++) {
        const int rbuf = s & 1;
        float* sP = sPart + rbuf * (8 * BPC * PSTR);

        // ---- prefetch x_proj gate inputs for epilogue (tid<128)
        float xr[4];
        if (tid < JPC * BPC) {
            const float* xpb = g_xp + ((size_t)((s * 16 + cg) * 8 + bg)) * 512
                             + bb * 64 + lj;
            #pragma unroll
            for (int gate = 0; gate < 4; gate++)
                xr[gate] = __ldg(xpb + gate * 16);
        }

        // ---- 2-deep pipelined bulk poll on tagged producer words
        const unsigned long long* pA = &g_hx[rbuf][bg][2 * w][4 * lane];
        const unsigned long long* pB = &g_hx[rbuf][bg][2 * w + 1][4 * lane];
        unsigned long long ua[4], ub[4], va[4], vb[4];
        const unsigned exp_tag = (unsigned)s;
        #pragma unroll
        for (int i = 0; i < 4; i++) { ua[i] = ld_relaxed_u64(pA + i);
                                      ub[i] = ld_relaxed_u64(pB + i); }
        #pragma unroll
        for (int i = 0; i < 4; i++) { va[i] = ld_relaxed_u64(pA + i);
                                      vb[i] = ld_relaxed_u64(pB + i); }
        for (;;) {
            bool oku = ((unsigned)(ua[0] >> 32) == exp_tag) &&
                       ((unsigned)(ua[1] >> 32) == exp_tag) &&
                       ((unsigned)(ua[2] >> 32) == exp_tag) &&
                       ((unsigned)(ua[3] >> 32) == exp_tag) &&
                       ((unsigned)(ub[0] >> 32) == exp_tag) &&
                       ((unsigned)(ub[1] >> 32) == exp_tag) &&
                       ((unsigned)(ub[2] >> 32) == exp_tag) &&
                       ((unsigned)(ub[3] >> 32) == exp_tag);
            if (__all_sync(0xffffffffu, oku)) break;
            #pragma unroll
            for (int i = 0; i < 4; i++) { ua[i] = ld_relaxed_u64(pA + i);
                                          ub[i] = ld_relaxed_u64(pB + i); }
            bool okv = ((unsigned)(va[0] >> 32) == exp_tag) &&
                       ((unsigned)(va[1] >> 32) == exp_tag) &&
                       ((unsigned)(va[2] >> 32) == exp_tag) &&
                       ((unsigned)(va[3] >> 32) == exp_tag) &&
                       ((unsigned)(vb[0] >> 32) == exp_tag) &&
                       ((unsigned)(vb[1] >> 32) == exp_tag) &&
                       ((unsigned)(vb[2] >> 32) == exp_tag) &&
                       ((unsigned)(vb[3] >> 32) == exp_tag);
            if (__all_sync(0xffffffffu, okv)) {
                #pragma unroll
                for (int i = 0; i < 4; i++) { ua[i] = va[i]; ub[i] = vb[i]; }
                break;
            }
            #pragma unroll
            for (int i = 0; i < 4; i++) { va[i] = ld_relaxed_u64(pA + i);
                                          vb[i] = ld_relaxed_u64(pB + i); }
        }

        // ---- unpack h and stage into my private sH rows
        asm volatile("st.shared.v4.f32 [%0], {%1,%2,%3,%4};"
                     :: "r"(hstore),
                        "f"(__uint_as_float((unsigned)ua[0])),
                        "f"(__uint_as_float((unsigned)ua[1])),
                        "f"(__uint_as_float((unsigned)ua[2])),
                        "f"(__uint_as_float((unsigned)ua[3])));
        asm volatile("st.shared.v4.f32 [%0], {%1,%2,%3,%4};"
                     :: "r"(hstore + 512),
                        "f"(__uint_as_float((unsigned)ub[0])),
                        "f"(__uint_as_float((unsigned)ub[1])),
                        "f"(__uint_as_float((unsigned)ub[2])),
                        "f"(__uint_as_float((unsigned)ub[3])));
        __syncwarp();

        // ---- GEMM: per k: 1 broadcast LDS.128 + 4 splats + 8 FMA2
        unsigned long long acc[2][4];
        #pragma unroll
        for (int p = 0; p < 2; p++)
            #pragma unroll
            for (int i = 0; i < 4; i++) acc[p][i] = 0ull;

        #pragma unroll
        for (int k = 0; k < KC; k++) {
            float h0, h1, h2f, h3;
            asm volatile("ld.shared.v4.f32 {%0,%1,%2,%3}, [%4];"
                         : "=f"(h0), "=f"(h1), "=f"(h2f), "=f"(h3)
                         : "r"(hbase + k * 32));
            unsigned long long hh[4];
            asm("mov.b64 %0, {%1, %1};" : "=l"(hh[0]) : "f"(h0));
            asm("mov.b64 %0, {%1, %1};" : "=l"(hh[1]) : "f"(h1));
            asm("mov.b64 %0, {%1, %1};" : "=l"(hh[2]) : "f"(h2f));
            asm("mov.b64 %0, {%1, %1};" : "=l"(hh[3]) : "f"(h3));
            #pragma unroll
            for (int i = 0; i < 4; i++) {
                asm volatile("fma.rn.f32x2 %0, %1, %2, %0;"
                             : "+l"(acc[0][i]) : "l"(hh[i]), "l"(wreg[0][k]));
                asm volatile("fma.rn.f32x2 %0, %1, %2, %0;"
                             : "+l"(acc[1][i]) : "l"(hh[i]), "l"(wreg[1][k]));
            }
        }

        // ---- write partials
        #pragma unroll
        for (int i = 0; i < 4; i++) {
            int row = (w * BPC + 4 * hw + i) * PSTR;
            *reinterpret_cast<unsigned long long*>(sP + row + c0)     = acc[0][i];
            *reinterpret_cast<unsigned long long*>(sP + row + c0 + 2) = acc[1][i];
        }

        // ---- barrier split: epi warps sync; helper warps arrive & run ahead
        if (tid < JPC * BPC) {
            if ((s & 1) == 0)
                asm volatile("bar.sync 1, 256;" ::: "memory");
            else
                asm volatile("bar.sync 2, 256;" ::: "memory");

            // epilogue: reduce 8 partials, activations, tagged publish
            float g4[4];
            #pragma unroll
            for (int gate = 0; gate < 4; gate++) {
                int c = gate * JPC + lj;
                float v = xr[gate];
                #pragma unroll
                for (int q = 0; q < 8; q++)
                    v += sP[(q * BPC + bb) * PSTR + c];
                g4[gate] = v;
            }
            float e0 = __expf(-g4[0]);
            float e1 = __expf(-g4[1]);
            float e2 = __expf(-2.0f * g4[2]);
            float e3 = __expf(-g4[3]);
            float ig = fast_sig(e0);
            float fg = fast_sig(e1);
            float gg = __fdividef(2.0f, 1.0f + e2) - 1.0f;
            float og = fast_sig(e3);
            float cnew = fg * sC[tid] + ig * gg;
            sC[tid] = cnew;
            float ech = __expf(-2.0f * cnew);
            float hnew = og * (__fdividef(2.0f, 1.0f + ech) - 1.0f);

            unsigned long long pk;
            asm("mov.b64 %0, {%1, %2};"
                : "=l"(pk) : "r"(__float_as_uint(hnew)), "r"((unsigned)(s + 1)));
            asm volatile("st.relaxed.gpu.global.u64 [%0], %1;"
                         :: "l"(&g_hx[rbuf ^ 1][bg][cg][tid]), "l"(pk)
                         : "memory");
        } else {
            if ((s & 1) == 0)
                asm volatile("bar.arrive 1, 256;" ::: "memory");
            else
                asm volatile("bar.arrive 2, 256;" ::: "memory");
            // helpers run ahead into step s+1 (sH rows warp-private,
            // sPart double-buffered; data deps bound skew to < 2 steps)
        }
    }
}

// ---------------------------------------------------------------------------
// final FC: out[b][d] = sum_k h_final[k][b] * fc_w[k][d] + fc_b[d]
// h_2048 (tag 2048) lives in g_hx[0][bg][k>>4][(k&15)*8+bb] low bits
// ---------------------------------------------------------------------------
__global__ void fc_kernel(const float* __restrict__ fc_w,
                          const float* __restrict__ fc_b,
                          float* __restrict__ out) {
    int b = blockIdx.x;
    int d = threadIdx.x;
    int bg = b >> 3, bb = b & 7;
    float acc = fc_b[d];
    #pragma unroll 8
    for (int k = 0; k < HID; k++) {
        unsigned long long v = g_hx[0][bg][k >> 4][(k & 15) * 8 + bb];
        acc += __uint_as_float((unsigned)v) * fc_w[k * DOUT + d];
    }
    out[b * DOUT + d] = acc;
}

// ---------------------------------------------------------------------------
extern "C" void kernel_launch(void* const* d_in, const int* in_sizes, int n_in,
                              void* d_out, int out_size) {
    const float* x    = (const float*)d_in[0];
    const float* W_x  = (const float*)d_in[1];
    const float* W_h  = (const float*)d_in[2];
    const float* bvec = (const float*)d_in[3];
    const float* fc_w = (const float*)d_in[4];
    const float* fc_b = (const float*)d_in[5];
    float* out = (float*)d_out;

    cudaFuncSetAttribute(xproj_kernel,
                         cudaFuncAttributeMaxDynamicSharedMemorySize, XPK_BYTES);
    cudaFuncSetAttribute(lstm_scan_kernel,
                         cudaFuncAttributeMaxDynamicSharedMemorySize, SMEM_BYTES);

    init_kernel<<<(2 * 8 * 16 * JPC * BPC + 255) / 256, 256>>>();
    xproj_kernel<<<dim3(TSTEPS / 16, 8), NTHREADS, XPK_BYTES>>>(x, W_x, bvec);
    lstm_scan_kernel<<<NCTA, NTHREADS, SMEM_BYTES>>>(W_h);
    fc_kernel<<<BATCH, DOUT>>>(fc_w, fc_b, out);
}

// round 15
// speedup vs baseline: 1.5522x; 1.2925x over previous
#include <cuda_runtime.h>
#include <cstdint>

// Problem constants
#define BATCH 64
#define TSTEPS 2048
#define DIN 128
#define HID 256
#define DOUT 128
#define G4H (4*HID)        // 1024

// Scan tiling: 16 column-groups x 8 batch-groups = 128 CTAs
#define NCTA 128
#define JPC 16             // hidden units per CTA
#define NCOL 64            // gate columns per CTA
#define BPC 8              // batches per CTA
#define KC 32              // K per warp (8 warps)
#define NTHREADS 256

// SMEM (floats)
#define SWSTR 66                         // sW2 [k][c] staging stride
#define PSTR 70                          // sPart row stride
#define SM_SW2   0                       // 256*66 = 16896 (setup only)
#define SM_H     (SM_SW2 + 256*SWSTR)    // sH [k(256)][b(8)] = 2048
#define SM_PART  (SM_H + 256*8)          // 2 x 8 x 8 x PSTR = 8960
#define SM_C     (SM_PART + 2*8*8*PSTR)  // 128
#define SM_FLOATS (SM_C + 128)
#define SMEM_BYTES (SM_FLOATS*4)         // ~113 KB

// x_proj kernel smem
#define XP_XSTRIDE 133
#define XP_WSTRIDE 132
#define XPK_SX    0
#define XPK_SW    (128*XP_XSTRIDE)
#define XPK_FLOATS (XPK_SW + 128*XP_WSTRIDE)
#define XPK_BYTES (XPK_FLOATS*4)

// Global scratch
__device__ __align__(16) float g_xp[(size_t)TSTEPS * 16 * 8 * 512];      // [t][cg][bg][bb*64+c]
// tagged h words: {hi32 = step tag, lo32 = h bits}; [buf][bg][cg][lj*8+bb]
__device__ __align__(16) unsigned long long g_hx[2][8][16][JPC*BPC];

__device__ __forceinline__ uint32_t smem_u32(const void* p) {
    return (uint32_t)__cvta_generic_to_shared(p);
}
__device__ __forceinline__ unsigned long long ld_relaxed_u64(
        const unsigned long long* p) {
    unsigned long long v;
    asm volatile("ld.relaxed.gpu.global.u64 %0, [%1];"
                 : "=l"(v) : "l"(p) : "memory");
    return v;
}

// ---------------------------------------------------------------------------
__global__ void init_kernel() {
    int i = blockIdx.x * blockDim.x + threadIdx.x;
    int total = 2 * 8 * 16 * JPC * BPC;
    if (i < total) ((unsigned long long*)g_hx)[i] = 0ull;  // tag 0, h = 0
}

// ---------------------------------------------------------------------------
// x_proj: g_xp[t][cg][bg][bb*64 + gate*16+lj] = x[b,t,:] . W_x[:, gcol] + bias
// ---------------------------------------------------------------------------
__global__ void __launch_bounds__(NTHREADS, 1)
xproj_kernel(const float* __restrict__ x,
             const float* __restrict__ W_x,
             const float* __restrict__ bias) {
    extern __shared__ float smem[];
    float* sX = smem + XPK_SX;
    float* sW = smem + XPK_SW;

    const int tid  = threadIdx.x;
    const int tblk = blockIdx.x;
    const int bg   = blockIdx.y;

    for (int idx = tid; idx < 128 * 32; idx += NTHREADS) {
        int r = idx >> 5, f4 = idx & 31;
        int tt = r >> 3, bb = r & 7;
        int b = bg * 8 + bb, t = tblk * 16 + tt;
        float4 v = __ldg(reinterpret_cast<const float4*>(
            x + ((size_t)b * TSTEPS + t) * DIN) + f4);
        float* dst = sX + r * XP_XSTRIDE + f4 * 4;
        dst[0] = v.x; dst[1] = v.y; dst[2] = v.z; dst[3] = v.w;
    }

    const int cq = tid & 7;
    const int rg = tid >> 3;

    for (int p = 0; p < 8; p++) {
        const int cp0 = p * 128;
        __syncthreads();
        for (int idx = tid; idx < 128 * 32; idx += NTHREADS) {
            int d = idx >> 5, c4 = idx & 31;
            float4 v = __ldg(reinterpret_cast<const float4*>(
                W_x + (size_t)d * G4H + cp0) + c4);
            float* dst = sW + d * XP_WSTRIDE + c4 * 4;
            dst[0] = v.x; dst[1] = v.y; dst[2] = v.z; dst[3] = v.w;
        }
        __syncthreads();

        unsigned long long acc[4][8];
        #pragma unroll
        for (int qq = 0; qq < 8; qq++) {
            float2 bv = __ldg(reinterpret_cast<const float2*>(
                bias + cp0 + 2 * (cq + 8 * qq)));
            unsigned long long bu;
            asm("mov.b64 %0, {%1, %2};" : "=l"(bu) : "f"(bv.x), "f"(bv.y));
            #pragma unroll
            for (int rr = 0; rr < 4; rr++) acc[rr][qq] = bu;
        }

        #pragma unroll 4
        for (int d = 0; d < 128; d++) {
            unsigned long long x2[4];
            #pragma unroll
            for (int rr = 0; rr < 4; rr++) {
                float xv = sX[(rg * 4 + rr) * XP_XSTRIDE + d];
                asm("mov.b64 %0, {%1, %1};" : "=l"(x2[rr]) : "f"(xv));
            }
            const uint32_t wrow = smem_u32(sW + d * XP_WSTRIDE + 2 * cq);
            #pragma unroll
            for (int qq = 0; qq < 8; qq++) {
                unsigned long long w2;
                asm volatile("ld.shared.u64 %0, [%1];"
                             : "=l"(w2) : "r"(wrow + qq * 64));
                #pragma unroll
                for (int rr = 0; rr < 4; rr++)
                    asm volatile("fma.rn.f32x2 %0, %1, %2, %0;"
                                 : "+l"(acc[rr][qq]) : "l"(x2[rr]), "l"(w2));
            }
        }

        #pragma unroll
        for (int rr = 0; rr < 4; rr++) {
            int r = rg * 4 + rr;
            int tt = r >> 3, bb = r & 7;
            int t = tblk * 16 + tt;
            #pragma unroll
            for (int qq = 0; qq < 8; qq++) {
                int cglob = cp0 + 2 * (cq + 8 * qq);
                int gate = cglob >> 8, rem = cglob & 255;
                int cg = rem >> 4, lj = rem & 15;
                float lo, hi;
                asm("mov.b64 {%0,%1}, %2;" : "=f"(lo), "=f"(hi) : "l"(acc[rr][qq]));
                float2* dst = reinterpret_cast<float2*>(
                    g_xp + ((size_t)((t * 16 + cg) * 8 + bg)) * 512
                         + bb * 64 + gate * 16 + lj);
                *dst = make_float2(lo, hi);
            }
        }
    }
}

// ---------------------------------------------------------------------------
// persistent LSTM scan: W_h in registers; self-tagging h words (R9 poll);
// epilogue reordered for earliest publish.
// ---------------------------------------------------------------------------
__global__ void __launch_bounds__(NTHREADS, 1)
lstm_scan_kernel(const float* __restrict__ W_h) {
    extern __shared__ float smem[];
    float* sW2   = smem + SM_SW2;   // [k][c] staging (setup only)
    float* sH    = smem + SM_H;     // [k(256)][b(8)]
    float* sPart = smem + SM_PART;  // [buf][w][b][c] stride PSTR
    float* sC    = smem + SM_C;     // [lj*8+bb]

    const int tid = threadIdx.x;
    const int cg  = blockIdx.x & 15;
    const int bg  = blockIdx.x >> 4;
    const int j0  = cg * JPC;

    // ---- stage W_h slice as [k][c] then load into registers
    for (int idx = tid; idx < KC * 8 * NCOL; idx += NTHREADS) {
        int k = idx >> 6, c = idx & 63;
        int gate = c >> 4, lj = c & 15;
        sW2[k * SWSTR + c] = W_h[(size_t)k * G4H + gate * HID + j0 + lj];
    }
    if (tid < JPC * BPC) sC[tid] = 0.0f;
    __syncthreads();

    const int w    = tid >> 5;            // warp = k-chunk
    const int lane = tid & 31;
    const int hw   = lane >> 4;           // batch half
    const int lc   = lane & 15;           // owns cols 4lc..4lc+3
    const int k0   = w * KC;
    const int c0   = 4 * lc;

    unsigned long long wreg[2][KC];       // [pair][k]
    {
        const uint32_t wb = smem_u32(sW2 + k0 * SWSTR + c0);
        #pragma unroll
        for (int k = 0; k < KC; k++) {
            asm volatile("ld.shared.u64 %0, [%1];"
                         : "=l"(wreg[0][k]) : "r"(wb + k * (SWSTR * 4)));
            asm volatile("ld.shared.u64 %0, [%1];"
                         : "=l"(wreg[1][k]) : "r"(wb + k * (SWSTR * 4) + 8));
        }
    }
    __syncthreads();   // sW2 dead after this

    const uint32_t hbase  = smem_u32(sH + k0 * BPC + 4 * hw);
    const uint32_t hstore = smem_u32(sH + k0 * BPC) + lane * 16;

    const int lj = tid >> 3;              // epilogue decode (tid<128)
    const int bb = tid & 7;

    for (int s = 0; s < TSTEPS; s++) {
        const int rbuf = s & 1;
        float* sP = sPart + rbuf * (8 * BPC * PSTR);

        // ---- prefetch x_proj gate inputs for epilogue (tid<128)
        float xr[4];
        if (tid < JPC * BPC) {
            const float* xpb = g_xp + ((size_t)((s * 16 + cg) * 8 + bg)) * 512
                             + bb * 64 + lj;
            #pragma unroll
            for (int gate = 0; gate < 4; gate++)
                xr[gate] = __ldcg(xpb + gate * 16);
        }

        // ---- R9 bulk poll on tagged producer words (data in hand at detect)
        const unsigned long long* pA = &g_hx[rbuf][bg][2 * w][4 * lane];
        const unsigned long long* pB = &g_hx[rbuf][bg][2 * w + 1][4 * lane];
        unsigned long long va[4], vb[4];
        const unsigned exp_tag = (unsigned)s;
        #pragma unroll
        for (int i = 0; i < 4; i++) { va[i] = ld_relaxed_u64(pA + i);
                                      vb[i] = ld_relaxed_u64(pB + i); }
        for (;;) {
            bool all_ok = true;
            #pragma unroll
            for (int i = 0; i < 4; i++) {
                if ((unsigned)(va[i] >> 32) != exp_tag) {
                    va[i] = ld_relaxed_u64(pA + i); all_ok = false;
                }
                if ((unsigned)(vb[i] >> 32) != exp_tag) {
                    vb[i] = ld_relaxed_u64(pB + i); all_ok = false;
                }
            }
            if (__all_sync(0xffffffffu, all_ok)) break;
        }

        // ---- unpack h and stage into my private sH rows
        asm volatile("st.shared.v4.f32 [%0], {%1,%2,%3,%4};"
                     :: "r"(hstore),
                        "f"(__uint_as_float((unsigned)va[0])),
                        "f"(__uint_as_float((unsigned)va[1])),
                        "f"(__uint_as_float((unsigned)va[2])),
                        "f"(__uint_as_float((unsigned)va[3])));
        asm volatile("st.shared.v4.f32 [%0], {%1,%2,%3,%4};"
                     :: "r"(hstore + 512),
                        "f"(__uint_as_float((unsigned)vb[0])),
                        "f"(__uint_as_float((unsigned)vb[1])),
                        "f"(__uint_as_float((unsigned)vb[2])),
                        "f"(__uint_as_float((unsigned)vb[3])));
        __syncwarp();

        // ---- GEMM: per k: 1 broadcast LDS.128 + 4 splats + 8 FMA2
        unsigned long long acc[2][4];
        #pragma unroll
        for (int p = 0; p < 2; p++)
            #pragma unroll
            for (int i = 0; i < 4; i++) acc[p][i] = 0ull;

        #pragma unroll
        for (int k = 0; k < KC; k++) {
            float h0, h1, h2f, h3;
            asm volatile("ld.shared.v4.f32 {%0,%1,%2,%3}, [%4];"
                         : "=f"(h0), "=f"(h1), "=f"(h2f), "=f"(h3)
                         : "r"(hbase + k * 32));
            unsigned long long hh[4];
            asm("mov.b64 %0, {%1, %1};" : "=l"(hh[0]) : "f"(h0));
            asm("mov.b64 %0, {%1, %1};" : "=l"(hh[1]) : "f"(h1));
            asm("mov.b64 %0, {%1, %1};" : "=l"(hh[2]) : "f"(h2f));
            asm("mov.b64 %0, {%1, %1};" : "=l"(hh[3]) : "f"(h3));
            #pragma unroll
            for (int i = 0; i < 4; i++) {
                asm volatile("fma.rn.f32x2 %0, %1, %2, %0;"
                             : "+l"(acc[0][i]) : "l"(hh[i]), "l"(wreg[0][k]));
                asm volatile("fma.rn.f32x2 %0, %1, %2, %0;"
                             : "+l"(acc[1][i]) : "l"(hh[i]), "l"(wreg[1][k]));
            }
        }

        // ---- write partials
        #pragma unroll
        for (int i = 0; i < 4; i++) {
            int row = (w * BPC + 4 * hw + i) * PSTR;
            *reinterpret_cast<unsigned long long*>(sP + row + c0)     = acc[0][i];
            *reinterpret_cast<unsigned long long*>(sP + row + c0 + 2) = acc[1][i];
        }
        __syncthreads();

        // ---- epilogue (warps 0-3): reordered for earliest publish
        if (tid < JPC * BPC) {
            // reduce gates in dependence order: g (2), i (0), f (1), o (3)
            float g4[4];
            #pragma unroll
            for (int gate = 0; gate < 4; gate++) {
                int c = gate * JPC + lj;
                float v = xr[gate];
                #pragma unroll
                for (int q = 0; q < 8; q++)
                    v += sP[(q * BPC + bb) * PSTR + c];
                g4[gate] = v;
            }
            // issue all MUFU exps back-to-back (pipelined)
            float e2 = __expf(-2.0f * g4[2]);   // tanh(g) path (critical)
            float e0 = __expf(-g4[0]);          // i
            float e1 = __expf(-g4[1]);          // f
            float e3 = __expf(-g4[3]);          // o (parallel branch)
            float gg = __fdividef(2.0f, 1.0f + e2) - 1.0f;
            float ig = __fdividef(1.0f, 1.0f + e0);
            float fg = __fdividef(1.0f, 1.0f + e1);
            float cnew = fg * sC[tid] + ig * gg;
            float ech = __expf(-2.0f * cnew);
            float og = __fdividef(1.0f, 1.0f + e3);
            float hnew = og * (__fdividef(2.0f, 1.0f + ech) - 1.0f);

            // publish FIRST (inter-CTA critical path), then local state
            unsigned long long pk;
            asm("mov.b64 %0, {%1, %2};"
                : "=l"(pk) : "r"(__float_as_uint(hnew)), "r"((unsigned)(s + 1)));
            asm volatile("st.relaxed.gpu.global.u64 [%0], %1;"
                         :: "l"(&g_hx[rbuf ^ 1][bg][cg][tid]), "l"(pk)
                         : "memory");
            sC[tid] = cnew;
        }
    }
}

// ---------------------------------------------------------------------------
// final FC: out[b][d] = sum_k h_final[k][b] * fc_w[k][d] + fc_b[d]
// h_2048 (tag 2048) lives in g_hx[0][bg][k>>4][(k&15)*8+bb] low bits
// ---------------------------------------------------------------------------
__global__ void fc_kernel(const float* __restrict__ fc_w,
                          const float* __restrict__ fc_b,
                          float* __restrict__ out) {
    int b = blockIdx.x;
    int d = threadIdx.x;
    int bg = b >> 3, bb = b & 7;
    float acc = fc_b[d];
    #pragma unroll 8
    for (int k = 0; k < HID; k++) {
        unsigned long long v = g_hx[0][bg][k >> 4][(k & 15) * 8 + bb];
        acc += __uint_as_float((unsigned)v) * fc_w[k * DOUT + d];
    }
    out[b * DOUT + d] = acc;
}

// ---------------------------------------------------------------------------
extern "C" void kernel_launch(void* const* d_in, const int* in_sizes, int n_in,
                              void* d_out, int out_size) {
    const float* x    = (const float*)d_in[0];
    const float* W_x  = (const float*)d_in[1];
    const float* W_h  = (const float*)d_in[2];
    const float* bvec = (const float*)d_in[3];
    const float* fc_w = (const float*)d_in[4];
    const float* fc_b = (const float*)d_in[5];
    float* out = (float*)d_out;

    cudaFuncSetAttribute(xproj_kernel,
                         cudaFuncAttributeMaxDynamicSharedMemorySize, XPK_BYTES);
    cudaFuncSetAttribute(lstm_scan_kernel,
                         cudaFuncAttributeMaxDynamicSharedMemorySize, SMEM_BYTES);

    init_kernel<<<(2 * 8 * 16 * JPC * BPC + 255) / 256, 256>>>();
    xproj_kernel<<<dim3(TSTEPS / 16, 8), NTHREADS, XPK_BYTES>>>(x, W_x, bvec);
    lstm_scan_kernel<<<NCTA, NTHREADS, SMEM_BYTES>>>(W_h);
    fc_kernel<<<BATCH, DOUT>>>(fc_w, fc_b, out);
}

// round 16
// speedup vs baseline: 1.6533x; 1.0651x over previous
#include <cuda_runtime.h>
#include <cstdint>

// Problem constants
#define BATCH 64
#define TSTEPS 2048
#define DIN 128
#define HID 256
#define DOUT 128
#define G4H (4*HID)        // 1024

// Scan tiling: 16 column-groups x 8 batch-groups = 128 CTAs
#define NCTA 128
#define JPC 16             // hidden units per CTA
#define NCOL 64            // gate columns per CTA
#define BPC 8              // batches per CTA
#define KC 32              // K per warp (8 warps)
#define NTHREADS 256

// SMEM (floats)
#define SWSTR 66                         // sW2 [k][c] staging stride
#define PSTR 70                          // sPart row stride
#define SM_SW2   0                       // 256*66 = 16896 (setup only)
#define SM_H     (SM_SW2 + 256*SWSTR)    // sH [k(256)][b(8)] = 2048
#define SM_PART  (SM_H + 256*8)          // 2 x 8 x 8 x PSTR = 8960
#define SM_C     (SM_PART + 2*8*8*PSTR)  // 128
#define SM_FLOATS (SM_C + 128)
#define SMEM_BYTES (SM_FLOATS*4)         // ~113 KB

// x_proj kernel smem
#define XP_XSTRIDE 133
#define XP_WSTRIDE 132
#define XPK_SX    0
#define XPK_SW    (128*XP_XSTRIDE)
#define XPK_FLOATS (XPK_SW + 128*XP_WSTRIDE)
#define XPK_BYTES (XPK_FLOATS*4)

// Global scratch
__device__ __align__(16) float g_xp[(size_t)TSTEPS * 16 * 8 * 512];      // [t][cg][bg][bb*64+c]
// tagged h words: {hi32 = step tag, lo32 = h bits}; [buf][bg][cg][lj*8+bb]
__device__ __align__(16) unsigned long long g_hx[2][8][16][JPC*BPC];

__device__ __forceinline__ uint32_t smem_u32(const void* p) {
    return (uint32_t)__cvta_generic_to_shared(p);
}
__device__ __forceinline__ unsigned long long ld_relaxed_u64(
        const unsigned long long* p) {
    unsigned long long v;
    asm volatile("ld.relaxed.gpu.global.u64 %0, [%1];"
                 : "=l"(v) : "l"(p) : "memory");
    return v;
}

// stage one 16-byte packet (4 tagged words' low 32 bits) into sH
#define STAGE_BLOCK(vx, OFF)                                              \
    asm volatile("st.shared.v4.f32 [%0], {%1,%2,%3,%4};"                  \
                 :: "r"(hstore + (OFF)),                                  \
                    "f"(__uint_as_float((unsigned)(vx)[0])),              \
                    "f"(__uint_as_float((unsigned)(vx)[1])),              \
                    "f"(__uint_as_float((unsigned)(vx)[2])),              \
                    "f"(__uint_as_float((unsigned)(vx)[3])))

// half GEMM over k = KOFF .. KOFF+15 (accumulates into acc)
#define GEMM_HALF(KOFF)                                                   \
    do {                                                                  \
        _Pragma("unroll")                                                 \
        for (int k = 0; k < 16; k++) {                                    \
            float h0, h1, h2f, h3;                                        \
            asm volatile("ld.shared.v4.f32 {%0,%1,%2,%3}, [%4];"          \
                         : "=f"(h0), "=f"(h1), "=f"(h2f), "=f"(h3)        \
                         : "r"(hbase + ((KOFF) + k) * 32));               \
            unsigned long long hh[4];                                     \
            asm("mov.b64 %0, {%1, %1};" : "=l"(hh[0]) : "f"(h0));         \
            asm("mov.b64 %0, {%1, %1};" : "=l"(hh[1]) : "f"(h1));         \
            asm("mov.b64 %0, {%1, %1};" : "=l"(hh[2]) : "f"(h2f));        \
            asm("mov.b64 %0, {%1, %1};" : "=l"(hh[3]) : "f"(h3));         \
            _Pragma("unroll")                                             \
            for (int i = 0; i < 4; i++) {                                 \
                asm volatile("fma.rn.f32x2 %0, %1, %2, %0;"               \
                    : "+l"(acc[0][i]) : "l"(hh[i]), "l"(wreg[0][(KOFF)+k])); \
                asm volatile("fma.rn.f32x2 %0, %1, %2, %0;"               \
                    : "+l"(acc[1][i]) : "l"(hh[i]), "l"(wreg[1][(KOFF)+k])); \
            }                                                             \
        }                                                                 \
    } while (0)

// poll remaining stale words of one block until all tags match
#define POLL_BLOCK(vx, px)                                                \
    do {                                                                  \
        for (;;) {                                                        \
            bool ok_ = true;                                              \
            _Pragma("unroll")                                             \
            for (int i = 0; i < 4; i++) {                                 \
                if ((unsigned)((vx)[i] >> 32) != exp_tag) {               \
                    (vx)[i] = ld_relaxed_u64((px) + i); ok_ = false;      \
                }                                                         \
            }                                                             \
            if (__all_sync(0xffffffffu, ok_)) break;                      \
        }                                                                 \
    } while (0)

// ---------------------------------------------------------------------------
__global__ void init_kernel() {
    int i = blockIdx.x * blockDim.x + threadIdx.x;
    int total = 2 * 8 * 16 * JPC * BPC;
    if (i < total) ((unsigned long long*)g_hx)[i] = 0ull;  // tag 0, h = 0
}

// ---------------------------------------------------------------------------
// x_proj: g_xp[t][cg][bg][bb*64 + gate*16+lj] = x[b,t,:] . W_x[:, gcol] + bias
// ---------------------------------------------------------------------------
__global__ void __launch_bounds__(NTHREADS, 1)
xproj_kernel(const float* __restrict__ x,
             const float* __restrict__ W_x,
             const float* __restrict__ bias) {
    extern __shared__ float smem[];
    float* sX = smem + XPK_SX;
    float* sW = smem + XPK_SW;

    const int tid  = threadIdx.x;
    const int tblk = blockIdx.x;
    const int bg   = blockIdx.y;

    for (int idx = tid; idx < 128 * 32; idx += NTHREADS) {
        int r = idx >> 5, f4 = idx & 31;
        int tt = r >> 3, bb = r & 7;
        int b = bg * 8 + bb, t = tblk * 16 + tt;
        float4 v = __ldg(reinterpret_cast<const float4*>(
            x + ((size_t)b * TSTEPS + t) * DIN) + f4);
        float* dst = sX + r * XP_XSTRIDE + f4 * 4;
        dst[0] = v.x; dst[1] = v.y; dst[2] = v.z; dst[3] = v.w;
    }

    const int cq = tid & 7;
    const int rg = tid >> 3;

    for (int p = 0; p < 8; p++) {
        const int cp0 = p * 128;
        __syncthreads();
        for (int idx = tid; idx < 128 * 32; idx += NTHREADS) {
            int d = idx >> 5, c4 = idx & 31;
            float4 v = __ldg(reinterpret_cast<const float4*>(
                W_x + (size_t)d * G4H + cp0) + c4);
            float* dst = sW + d * XP_WSTRIDE + c4 * 4;
            dst[0] = v.x; dst[1] = v.y; dst[2] = v.z; dst[3] = v.w;
        }
        __syncthreads();

        unsigned long long acc[4][8];
        #pragma unroll
        for (int qq = 0; qq < 8; qq++) {
            float2 bv = __ldg(reinterpret_cast<const float2*>(
                bias + cp0 + 2 * (cq + 8 * qq)));
            unsigned long long bu;
            asm("mov.b64 %0, {%1, %2};" : "=l"(bu) : "f"(bv.x), "f"(bv.y));
            #pragma unroll
            for (int rr = 0; rr < 4; rr++) acc[rr][qq] = bu;
        }

        #pragma unroll 4
        for (int d = 0; d < 128; d++) {
            unsigned long long x2[4];
            #pragma unroll
            for (int rr = 0; rr < 4; rr++) {
                float xv = sX[(rg * 4 + rr) * XP_XSTRIDE + d];
                asm("mov.b64 %0, {%1, %1};" : "=l"(x2[rr]) : "f"(xv));
            }
            const uint32_t wrow = smem_u32(sW + d * XP_WSTRIDE + 2 * cq);
            #pragma unroll
            for (int qq = 0; qq < 8; qq++) {
                unsigned long long w2;
                asm volatile("ld.shared.u64 %0, [%1];"
                             : "=l"(w2) : "r"(wrow + qq * 64));
                #pragma unroll
                for (int rr = 0; rr < 4; rr++)
                    asm volatile("fma.rn.f32x2 %0, %1, %2, %0;"
                                 : "+l"(acc[rr][qq]) : "l"(x2[rr]), "l"(w2));
            }
        }

        #pragma unroll
        for (int rr = 0; rr < 4; rr++) {
            int r = rg * 4 + rr;
            int tt = r >> 3, bb = r & 7;
            int t = tblk * 16 + tt;
            #pragma unroll
            for (int qq = 0; qq < 8; qq++) {
                int cglob = cp0 + 2 * (cq + 8 * qq);
                int gate = cglob >> 8, rem = cglob & 255;
                int cg = rem >> 4, lj = rem & 15;
                float lo, hi;
                asm("mov.b64 {%0,%1}, %2;" : "=f"(lo), "=f"(hi) : "l"(acc[rr][qq]));
                float2* dst = reinterpret_cast<float2*>(
                    g_xp + ((size_t)((t * 16 + cg) * 8 + bg)) * 512
                         + bb * 64 + gate * 16 + lj);
                *dst = make_float2(lo, hi);
            }
        }
    }
}

// ---------------------------------------------------------------------------
// persistent LSTM scan: W_h in registers; self-tagging h words;
// arrival-order split GEMM; publish-early epilogue.
// ---------------------------------------------------------------------------
__global__ void __launch_bounds__(NTHREADS, 1)
lstm_scan_kernel(const float* __restrict__ W_h) {
    extern __shared__ float smem[];
    float* sW2   = smem + SM_SW2;   // [k][c] staging (setup only)
    float* sH    = smem + SM_H;     // [k(256)][b(8)]
    float* sPart = smem + SM_PART;  // [buf][w][b][c] stride PSTR
    float* sC    = smem + SM_C;     // [lj*8+bb]

    const int tid = threadIdx.x;
    const int cg  = blockIdx.x & 15;
    const int bg  = blockIdx.x >> 4;
    const int j0  = cg * JPC;

    // ---- stage W_h slice as [k][c] then load into registers
    for (int idx = tid; idx < KC * 8 * NCOL; idx += NTHREADS) {
        int k = idx >> 6, c = idx & 63;
        int gate = c >> 4, lj = c & 15;
        sW2[k * SWSTR + c] = W_h[(size_t)k * G4H + gate * HID + j0 + lj];
    }
    if (tid < JPC * BPC) sC[tid] = 0.0f;
    __syncthreads();

    const int w    = tid >> 5;            // warp = k-chunk
    const int lane = tid & 31;
    const int hw   = lane >> 4;           // batch half
    const int lc   = lane & 15;           // owns cols 4lc..4lc+3
    const int k0   = w * KC;
    const int c0   = 4 * lc;

    unsigned long long wreg[2][KC];       // [pair][k]
    {
        const uint32_t wb = smem_u32(sW2 + k0 * SWSTR + c0);
        #pragma unroll
        for (int k = 0; k < KC; k++) {
            asm volatile("ld.shared.u64 %0, [%1];"
                         : "=l"(wreg[0][k]) : "r"(wb + k * (SWSTR * 4)));
            asm volatile("ld.shared.u64 %0, [%1];"
                         : "=l"(wreg[1][k]) : "r"(wb + k * (SWSTR * 4) + 8));
        }
    }
    __syncthreads();   // sW2 dead after this

    const uint32_t hbase  = smem_u32(sH + k0 * BPC + 4 * hw);
    const uint32_t hstore = smem_u32(sH + k0 * BPC) + lane * 16;

    const int lj = tid >> 3;              // epilogue decode (tid<128)
    const int bb = tid & 7;

    for (int s = 0; s < TSTEPS; s++) {
        const int rbuf = s & 1;
        float* sP = sPart + rbuf * (8 * BPC * PSTR);

        // ---- prefetch x_proj gate inputs for epilogue (tid<128)
        float xr[4];
        if (tid < JPC * BPC) {
            const float* xpb = g_xp + ((size_t)((s * 16 + cg) * 8 + bg)) * 512
                             + bb * 64 + lj;
            #pragma unroll
            for (int gate = 0; gate < 4; gate++)
                xr[gate] = __ldcg(xpb + gate * 16);
        }

        // ---- arrival-order poll + split GEMM on the two producer blocks
        const unsigned long long* pA = &g_hx[rbuf][bg][2 * w][4 * lane];
        const unsigned long long* pB = &g_hx[rbuf][bg][2 * w + 1][4 * lane];
        unsigned long long va[4], vb[4];
        const unsigned exp_tag = (unsigned)s;
        #pragma unroll
        for (int i = 0; i < 4; i++) { va[i] = ld_relaxed_u64(pA + i);
                                      vb[i] = ld_relaxed_u64(pB + i); }
        bool aReady, bReady;
        for (;;) {
            bool okA = true, okB = true;
            #pragma unroll
            for (int i = 0; i < 4; i++) {
                if ((unsigned)(va[i] >> 32) != exp_tag) okA = false;
                if ((unsigned)(vb[i] >> 32) != exp_tag) okB = false;
            }
            aReady = __all_sync(0xffffffffu, okA);
            bReady = __all_sync(0xffffffffu, okB);
            if (aReady || bReady) break;
            #pragma unroll
            for (int i = 0; i < 4; i++) {
                if ((unsigned)(va[i] >> 32) != exp_tag)
                    va[i] = ld_relaxed_u64(pA + i);
                if ((unsigned)(vb[i] >> 32) != exp_tag)
                    vb[i] = ld_relaxed_u64(pB + i);
            }
        }

        unsigned long long acc[2][4];
        #pragma unroll
        for (int p = 0; p < 2; p++)
            #pragma unroll
            for (int i = 0; i < 4; i++) acc[p][i] = 0ull;

        if (aReady) {
            // process A first; overlap its GEMM with B's wait
            STAGE_BLOCK(va, 0);
            __syncwarp();
            GEMM_HALF(0);
            if (!bReady) POLL_BLOCK(vb, pB);
            STAGE_BLOCK(vb, 512);
            __syncwarp();
            GEMM_HALF(16);
        } else {
            // B arrived first
            STAGE_BLOCK(vb, 512);
            __syncwarp();
            GEMM_HALF(16);
            POLL_BLOCK(va, pA);
            STAGE_BLOCK(va, 0);
            __syncwarp();
            GEMM_HALF(0);
        }

        // ---- write partials
        #pragma unroll
        for (int i = 0; i < 4; i++) {
            int row = (w * BPC + 4 * hw + i) * PSTR;
            *reinterpret_cast<unsigned long long*>(sP + row + c0)     = acc[0][i];
            *reinterpret_cast<unsigned long long*>(sP + row + c0 + 2) = acc[1][i];
        }
        __syncthreads();

        // ---- epilogue (warps 0-3): reordered for earliest publish
        if (tid < JPC * BPC) {
            float g4[4];
            #pragma unroll
            for (int gate = 0; gate < 4; gate++) {
                int c = gate * JPC + lj;
                float v = xr[gate];
                #pragma unroll
                for (int q = 0; q < 8; q++)
                    v += sP[(q * BPC + bb) * PSTR + c];
                g4[gate] = v;
            }
            float e2 = __expf(-2.0f * g4[2]);   // tanh(g) path (critical)
            float e0 = __expf(-g4[0]);          // i
            float e1 = __expf(-g4[1]);          // f
            float e3 = __expf(-g4[3]);          // o (parallel branch)
            float gg = __fdividef(2.0f, 1.0f + e2) - 1.0f;
            float ig = __fdividef(1.0f, 1.0f + e0);
            float fg = __fdividef(1.0f, 1.0f + e1);
            float cnew = fg * sC[tid] + ig * gg;
            float ech = __expf(-2.0f * cnew);
            float og = __fdividef(1.0f, 1.0f + e3);
            float hnew = og * (__fdividef(2.0f, 1.0f + ech) - 1.0f);

            // publish FIRST (inter-CTA critical path), then local state
            unsigned long long pk;
            asm("mov.b64 %0, {%1, %2};"
                : "=l"(pk) : "r"(__float_as_uint(hnew)), "r"((unsigned)(s + 1)));
            asm volatile("st.relaxed.gpu.global.u64 [%0], %1;"
                         :: "l"(&g_hx[rbuf ^ 1][bg][cg][tid]), "l"(pk)
                         : "memory");
            sC[tid] = cnew;
        }
    }
}

// ---------------------------------------------------------------------------
// final FC: out[b][d] = sum_k h_final[k][b] * fc_w[k][d] + fc_b[d]
// h_2048 (tag 2048) lives in g_hx[0][bg][k>>4][(k&15)*8+bb] low bits
// ---------------------------------------------------------------------------
__global__ void fc_kernel(const float* __restrict__ fc_w,
                          const float* __restrict__ fc_b,
                          float* __restrict__ out) {
    int b = blockIdx.x;
    int d = threadIdx.x;
    int bg = b >> 3, bb = b & 7;
    float acc = fc_b[d];
    #pragma unroll 8
    for (int k = 0; k < HID; k++) {
        unsigned long long v = g_hx[0][bg][k >> 4][(k & 15) * 8 + bb];
        acc += __uint_as_float((unsigned)v) * fc_w[k * DOUT + d];
    }
    out[b * DOUT + d] = acc;
}

// ---------------------------------------------------------------------------
extern "C" void kernel_launch(void* const* d_in, const int* in_sizes, int n_in,
                              void* d_out, int out_size) {
    const float* x    = (const float*)d_in[0];
    const float* W_x  = (const float*)d_in[1];
    const float* W_h  = (const float*)d_in[2];
    const float* bvec = (const float*)d_in[3];
    const float* fc_w = (const float*)d_in[4];
    const float* fc_b = (const float*)d_in[5];
    float* out = (float*)d_out;

    cudaFuncSetAttribute(xproj_kernel,
                         cudaFuncAttributeMaxDynamicSharedMemorySize, XPK_BYTES);
    cudaFuncSetAttribute(lstm_scan_kernel,
                         cudaFuncAttributeMaxDynamicSharedMemorySize, SMEM_BYTES);

    init_kernel<<<(2 * 8 * 16 * JPC * BPC + 255) / 256, 256>>>();
    xproj_kernel<<<dim3(TSTEPS / 16, 8), NTHREADS, XPK_BYTES>>>(x, W_x, bvec);
    lstm_scan_kernel<<<NCTA, NTHREADS, SMEM_BYTES>>>(W_h);
    fc_kernel<<<BATCH, DOUT>>>(fc_w, fc_b, out);
}